// round 16
// baseline (speedup 1.0000x reference)
#include <cuda_runtime.h>
#include <cuda_fp16.h>
#include <cstdint>

// Problem constants: B=2,H=16,N=4096,D=64,F=256
#define BHp   32
#define Np    4096
#define Dp    64
#define Fp    256
#define CHUNK 64
#define GROUPS 16
#define ROWS_PER_GROUP 256
#define CHUNKS_PER_GROUP 4
#define NJOBS (BHp * GROUPS)
#define NCTA  148
#define NT    512

// strides in halves
#define XS_S  72
#define PT_S  72
#define V_S   72
#define KP_S  264
#define QP_S  264
#define KVT_S 264

// smem byte offsets
#define OFF_PTH   0u
#define OFF_PTL   36864u
#define OFF_XSH   73728u
#define OFF_XSL   82944u
#define OFF_V0    92160u          // kside V stage 0 [64][72]
#define OFF_V1    101376u
#define OFF_KP0   110592u         // kside k' stage 0 [64][264]
#define OFF_KP1   144384u
#define OFF_RMK   178176u         // [4][64] f32
#define OFF_QP0   92160u          // qside q' stage 0 (aliases V/KP area)
#define OFF_QP1   125952u
#define OFF_KVT   159744u
#define OFF_KSS   193536u
#define OFF_RMQ   194560u
#define OFF_DNI   195584u         // [2][64] f32
#define OFF_FLG   196096u         // fullv[2], emptyv[2]
#define SMEM_TOTAL 196608u

__device__ float g_kv[BHp * Fp * Dp];
__device__ float g_ksum[BHp * Fp];
__device__ unsigned g_sync[BHp];
__device__ unsigned g_jobk;
__device__ unsigned g_jobq;

__global__ void zero_scratch() {
    int i = blockIdx.x * blockDim.x + threadIdx.x;
    if (i < BHp * Fp * Dp) g_kv[i] = 0.0f;
    if (i < BHp * Fp)      g_ksum[i] = 0.0f;
    if (i < BHp)           g_sync[i] = 0u;
    if (i == 0) { g_jobk = 0u; g_jobq = 0u; }
}

__device__ __forceinline__ void mma16816(float* c,
                                         unsigned a0, unsigned a1, unsigned a2, unsigned a3,
                                         unsigned b0, unsigned b1) {
    asm volatile(
        "mma.sync.aligned.m16n8k16.row.col.f32.f16.f16.f32 "
        "{%0,%1,%2,%3},{%4,%5,%6,%7},{%8,%9},{%0,%1,%2,%3};"
        : "+f"(c[0]), "+f"(c[1]), "+f"(c[2]), "+f"(c[3])
        : "r"(a0), "r"(a1), "r"(a2), "r"(a3), "r"(b0), "r"(b1));
}
__device__ __forceinline__ void ldsm4(unsigned* r, uint32_t a) {
    asm volatile("ldmatrix.sync.aligned.m8n8.x4.shared.b16 {%0,%1,%2,%3}, [%4];"
        : "=r"(r[0]), "=r"(r[1]), "=r"(r[2]), "=r"(r[3]) : "r"(a));
}
__device__ __forceinline__ void ldsm2(unsigned* r, uint32_t a) {
    asm volatile("ldmatrix.sync.aligned.m8n8.x2.shared.b16 {%0,%1}, [%2];"
        : "=r"(r[0]), "=r"(r[1]) : "r"(a));
}
__device__ __forceinline__ void ldsm4t(unsigned* r, uint32_t a) {
    asm volatile("ldmatrix.sync.aligned.m8n8.x4.trans.shared.b16 {%0,%1,%2,%3}, [%4];"
        : "=r"(r[0]), "=r"(r[1]), "=r"(r[2]), "=r"(r[3]) : "r"(a));
}
__device__ __forceinline__ void ldsm2t(unsigned* r, uint32_t a) {
    asm volatile("ldmatrix.sync.aligned.m8n8.x2.trans.shared.b16 {%0,%1}, [%2];"
        : "=r"(r[0]), "=r"(r[1]) : "r"(a));
}
#define NBAR(id) asm volatile("bar.sync %0, %1;" :: "r"(id), "r"(256) : "memory")

__device__ __forceinline__ void spin_ge(volatile int* p, int tgt) {
    while (*p < tgt) __nanosleep(64);
}

__device__ __forceinline__ void load_PT(const float* __restrict__ P,
                                        __half* PTh, __half* PTl, int tid) {
    for (int j = tid; j < Dp * Fp / 4; j += NT) {
        float4 v = ((const float4*)P)[j];
        int d = j >> 6;
        int f0 = (j & 63) * 4;
        #pragma unroll
        for (int u = 0; u < 4; u++) {
            float x = (&v.x)[u];
            __half hi = __float2half_rn(x);
            __half lo = __float2half_rn(x - __half2float(hi));
            PTh[(f0 + u) * PT_S + d] = hi;
            PTl[(f0 + u) * PT_S + d] = lo;
        }
    }
}

// ldmatrix lane-constant byte offsets
__device__ __forceinline__ int a4_const(int lane, int S) {
    return 2 * (((lane & 7) + ((lane >> 3) & 1) * 8) * S + (lane >> 4) * 8);
}
__device__ __forceinline__ int b2_const(int lane, int S) {
    return 2 * ((lane & 7) * S + ((lane >> 3) & 1) * 8);
}
__device__ __forceinline__ int a4t_const(int lane, int S) {
    return 2 * ((lane & 7) * S) + (((lane >> 3) & 1) * 16) + (((lane >> 4) & 1) * 2 * 8 * S);
}
__device__ __forceinline__ int b2t_const(int lane, int S) {
    int l = lane & 15;
    return 2 * ((l & 7) * S) + ((l >> 3) * 2 * 8 * S);
}

// 3-term projection, warp tile m32 x f64 (8 A-warps cover 64 rows x 256 f)
__device__ __forceinline__ void proj_mma(uint32_t xsh, uint32_t xsl,
                                         uint32_t pth, uint32_t ptl,
                                         int m0, int fbase, int a4c, int b2c,
                                         float pr[2][8][4]) {
    #pragma unroll
    for (int mi = 0; mi < 2; mi++)
        #pragma unroll
        for (int t = 0; t < 8; t++) {
            pr[mi][t][0] = 0.f; pr[mi][t][1] = 0.f; pr[mi][t][2] = 0.f; pr[mi][t][3] = 0.f;
        }
    #pragma unroll
    for (int k0 = 0; k0 < 64; k0 += 16) {
        unsigned ah[2][4], al[2][4];
        #pragma unroll
        for (int mi = 0; mi < 2; mi++) {
            uint32_t ab = 2u * ((m0 + mi * 16) * XS_S + k0) + a4c;
            ldsm4(ah[mi], xsh + ab);
            ldsm4(al[mi], xsl + ab);
        }
        #pragma unroll
        for (int t = 0; t < 8; t++) {
            uint32_t bb = 2u * ((fbase + t * 8) * PT_S + k0) + b2c;
            unsigned bh[2], bl[2];
            ldsm2(bh, pth + bb);
            ldsm2(bl, ptl + bb);
            #pragma unroll
            for (int mi = 0; mi < 2; mi++) {
                mma16816(pr[mi][t], ah[mi][0], ah[mi][1], ah[mi][2], ah[mi][3], bh[0], bh[1]);
                mma16816(pr[mi][t], ah[mi][0], ah[mi][1], ah[mi][2], ah[mi][3], bl[0], bl[1]);
                mma16816(pr[mi][t], al[mi][0], al[mi][1], al[mi][2], al[mi][3], bh[0], bh[1]);
            }
        }
    }
}

__device__ __forceinline__ void rowmax_store(float pr[2][8][4], float* RMAX,
                                             int m0, int seg, int lane) {
    const int r = lane >> 2;
    #pragma unroll
    for (int mi = 0; mi < 2; mi++) {
        float mlo = -3.4e38f, mhi = -3.4e38f;
        #pragma unroll
        for (int t = 0; t < 8; t++) {
            mlo = fmaxf(mlo, fmaxf(pr[mi][t][0], pr[mi][t][1]));
            mhi = fmaxf(mhi, fmaxf(pr[mi][t][2], pr[mi][t][3]));
        }
        #pragma unroll
        for (int off = 1; off <= 2; off <<= 1) {
            mlo = fmaxf(mlo, __shfl_xor_sync(0xffffffffu, mlo, off));
            mhi = fmaxf(mhi, __shfl_xor_sync(0xffffffffu, mhi, off));
        }
        if ((lane & 3) == 0) {
            RMAX[seg * 64 + m0 + mi * 16 + r]     = mlo;
            RMAX[seg * 64 + m0 + mi * 16 + 8 + r] = mhi;
        }
    }
}
__device__ __forceinline__ float rmax4(const float* RMAX, int row) {
    return fmaxf(fmaxf(RMAX[row], RMAX[64 + row]),
                 fmaxf(RMAX[128 + row], RMAX[192 + row]));
}
__device__ __forceinline__ unsigned pack2(__half a, __half b) {
    __half2 h = __halves2half2(a, b);
    return *(unsigned*)&h;
}

// ===========================================================================
// kside producer (warps 0-7): convert K, proj, exp -> KP[s]
// ===========================================================================
__device__ void kside_A(const float* __restrict__ K, int pair, int grp,
                        char* sm, uint32_t smu, int tid, int w, int lane,
                        volatile int* fullv, volatile int* emptyv) {
    __half* XSh = (__half*)(sm + OFF_XSH);
    __half* XSl = (__half*)(sm + OFF_XSL);
    float*  RMAX = (float*)(sm + OFF_RMK);
    const uint32_t xsh_u = smu + OFF_XSH, xsl_u = smu + OFF_XSL;
    const uint32_t pth_u = smu + OFF_PTH, ptl_u = smu + OFF_PTL;
    const int r  = lane >> 2;
    const int q2 = (lane & 3) * 2;
    const int a4c72 = a4_const(lane, 72);
    const int b2c72 = b2_const(lane, 72);

    for (int c = 0; c < CHUNKS_PER_GROUP; c++) {
        const int s = c & 1, rr_ = c >> 1;
        // load K chunk (LDG latency covered by B group's mma)
        const float4* ks = (const float4*)(K + ((size_t)pair * Np + grp * ROWS_PER_GROUP + c * CHUNK) * Dp);
        float4 kx[4];
        #pragma unroll
        for (int i = 0; i < 4; i++) kx[i] = ks[tid + 256 * i];
        // XS free (prior chunk proj done via its bars); store converts
        #pragma unroll
        for (int i = 0; i < 4; i++) {
            int j = tid + 256 * i;
            int row = j >> 4, d0 = (j & 15) * 4;
            __half h[4], l[4];
            #pragma unroll
            for (int u = 0; u < 4; u++) {
                float x = (&kx[i].x)[u];
                h[u] = __float2half_rn(x);
                l[u] = __float2half_rn(x - __half2float(h[u]));
            }
            *(uint2*)(XSh + row * XS_S + d0) = make_uint2(pack2(h[0], h[1]), pack2(h[2], h[3]));
            *(uint2*)(XSl + row * XS_S + d0) = make_uint2(pack2(l[0], l[1]), pack2(l[2], l[3]));
        }
        NBAR(1);

        const int m0 = (w >> 2) * 32;
        const int seg = w & 3;
        const int fbase = seg * 64;
        float pr[2][8][4];
        proj_mma(xsh_u, xsl_u, pth_u, ptl_u, m0, fbase, a4c72, b2c72, pr);
        rowmax_store(pr, RMAX, m0, seg, lane);
        NBAR(1);

        // wait stage free, then exp -> KP[s]
        if (rr_ > 0) spin_ge(emptyv + s, rr_);
        __threadfence_block();
        __half* KP = (__half*)(sm + (s ? OFF_KP1 : OFF_KP0));
        #pragma unroll
        for (int mi = 0; mi < 2; mi++) {
            const int mrow = m0 + mi * 16;
            const float Mlo = rmax4(RMAX, mrow + r);
            const float Mhi = rmax4(RMAX, mrow + 8 + r);
            #pragma unroll
            for (int t = 0; t < 8; t++) {
                const int f = fbase + t * 8 + q2;
                __half2 lo2 = __floats2half2_rn(__expf(pr[mi][t][0] - Mlo) * 0.0625f,
                                                __expf(pr[mi][t][1] - Mlo) * 0.0625f);
                __half2 hi2 = __floats2half2_rn(__expf(pr[mi][t][2] - Mhi) * 0.0625f,
                                                __expf(pr[mi][t][3] - Mhi) * 0.0625f);
                *(__half2*)(KP + (mrow + r) * KP_S + f)     = lo2;
                *(__half2*)(KP + (mrow + 8 + r) * KP_S + f) = hi2;
            }
        }
        NBAR(1);
        __threadfence_block();
        if (tid == 0) fullv[s] = rr_ + 1;
    }
}

// ===========================================================================
// kside consumer (warps 8-15): convert V, kv += k'^T v (+ksum ones col)
// ===========================================================================
__device__ void kside_B(const float* __restrict__ V, int pair, int grp,
                        char* sm, uint32_t smu, int tid, int w, int lane,
                        volatile int* fullv, volatile int* emptyv) {
    const int tidB = tid - 256;
    const int wB   = w - 8;
    const int r  = lane >> 2;
    const int q2 = (lane & 3) * 2;
    const int at4 = a4t_const(lane, KP_S);
    const int bt2 = b2t_const(lane, V_S);

    float accv[2][9][4];
    #pragma unroll
    for (int mi = 0; mi < 2; mi++)
        #pragma unroll
        for (int t = 0; t < 9; t++)
            #pragma unroll
            for (int u = 0; u < 4; u++) accv[mi][t][u] = 0.f;

    for (int c = 0; c < CHUNKS_PER_GROUP; c++) {
        const int s = c & 1, rr_ = c >> 1;
        const float4* vs4 = (const float4*)(V + ((size_t)pair * Np + grp * ROWS_PER_GROUP + c * CHUNK) * Dp);
        float4 vx[4];
        #pragma unroll
        for (int i = 0; i < 4; i++) vx[i] = vs4[tidB + 256 * i];
        __half* Vs = (__half*)(sm + (s ? OFF_V1 : OFF_V0));
        #pragma unroll
        for (int i = 0; i < 4; i++) {
            int j = tidB + 256 * i;
            int row = j >> 4, d0 = (j & 15) * 4;
            __half vh[4];
            #pragma unroll
            for (int u = 0; u < 4; u++) vh[u] = __float2half_rn((&vx[i].x)[u]);
            *(uint2*)(Vs + row * V_S + d0) = make_uint2(pack2(vh[0], vh[1]), pack2(vh[2], vh[3]));
        }

        spin_ge(fullv + s, rr_ + 1);
        __threadfence_block();
        NBAR(2);   // V[s] visible to all B warps; all past the spin

        const uint32_t kp_u = smu + (s ? OFF_KP1 : OFF_KP0);
        const uint32_t v_u  = smu + (s ? OFF_V1 : OFF_V0);
        const int fw = wB * 32;
        #pragma unroll
        for (int k0 = 0; k0 < 64; k0 += 16) {
            unsigned a[2][4];
            ldsm4t(a[0], kp_u + 2u * (k0 * KP_S + fw) + at4);
            ldsm4t(a[1], kp_u + 2u * (k0 * KP_S + fw + 16) + at4);
            #pragma unroll
            for (int t = 0; t < 9; t++) {
                unsigned b[2];
                ldsm2t(b, v_u + 2u * (k0 * V_S + t * 8) + bt2);
                mma16816(accv[0][t], a[0][0], a[0][1], a[0][2], a[0][3], b[0], b[1]);
                mma16816(accv[1][t], a[1][0], a[1][1], a[1][2], a[1][3], b[0], b[1]);
            }
        }
        NBAR(2);   // all B warps done reading KP[s]/V[s]
        __threadfence_block();
        if (tid == 256) emptyv[s] = rr_ + 1;
    }

    float* kvg = g_kv + (size_t)pair * Fp * Dp;
    #pragma unroll
    for (int mi = 0; mi < 2; mi++) {
        const int f0 = wB * 32 + mi * 16 + r;
        #pragma unroll
        for (int t = 0; t < 8; t++) {
            const int e = t * 8 + q2;
            atomicAdd(&kvg[f0 * Dp + e],           accv[mi][t][0]);
            atomicAdd(&kvg[f0 * Dp + e + 1],       accv[mi][t][1]);
            atomicAdd(&kvg[(f0 + 8) * Dp + e],     accv[mi][t][2]);
            atomicAdd(&kvg[(f0 + 8) * Dp + e + 1], accv[mi][t][3]);
        }
        if ((lane & 3) == 0) {
            atomicAdd(&g_ksum[(size_t)pair * Fp + f0],     accv[mi][8][0]);
            atomicAdd(&g_ksum[(size_t)pair * Fp + f0 + 8], accv[mi][8][2]);
        }
    }
    __threadfence();
    NBAR(2);
    if (tid == 256) atomicAdd(&g_sync[pair], 1u);
}

// ===========================================================================
// qside producer (warps 0-7): convert Q, proj, exp -> QP[s], denom -> DNI[s]
// ===========================================================================
__device__ void qside_A(const float* __restrict__ Q, int pair, int grp,
                        char* sm, uint32_t smu, int tid, int w, int lane,
                        volatile int* fullv, volatile int* emptyv) {
    __half* XSh = (__half*)(sm + OFF_XSH);
    __half* XSl = (__half*)(sm + OFF_XSL);
    float*  RMAX = (float*)(sm + OFF_RMQ);
    float*  KSS  = (float*)(sm + OFF_KSS);
    float*  DNI  = (float*)(sm + OFF_DNI);
    const uint32_t xsh_u = smu + OFF_XSH, xsl_u = smu + OFF_XSL;
    const uint32_t pth_u = smu + OFF_PTH, ptl_u = smu + OFF_PTL;
    const int r  = lane >> 2;
    const int q2 = (lane & 3) * 2;
    const int a4c72 = a4_const(lane, 72);
    const int b2c72 = b2_const(lane, 72);

    for (int c = 0; c < CHUNKS_PER_GROUP; c++) {
        const int s = c & 1, rr_ = c >> 1;
        const float4* qs = (const float4*)(Q + ((size_t)pair * Np + grp * ROWS_PER_GROUP + c * CHUNK) * Dp);
        float4 qx[4];
        #pragma unroll
        for (int i = 0; i < 4; i++) qx[i] = qs[tid + 256 * i];
        #pragma unroll
        for (int i = 0; i < 4; i++) {
            int j = tid + 256 * i;
            int row = j >> 4, d0 = (j & 15) * 4;
            __half h[4], l[4];
            #pragma unroll
            for (int u = 0; u < 4; u++) {
                float x = (&qx[i].x)[u];
                h[u] = __float2half_rn(x);
                l[u] = __float2half_rn(x - __half2float(h[u]));
            }
            *(uint2*)(XSh + row * XS_S + d0) = make_uint2(pack2(h[0], h[1]), pack2(h[2], h[3]));
            *(uint2*)(XSl + row * XS_S + d0) = make_uint2(pack2(l[0], l[1]), pack2(l[2], l[3]));
        }
        NBAR(1);

        const int m0 = (w >> 2) * 32;
        const int seg = w & 3;
        const int fbase = seg * 64;
        float pr[2][8][4];
        proj_mma(xsh_u, xsl_u, pth_u, ptl_u, m0, fbase, a4c72, b2c72, pr);
        rowmax_store(pr, RMAX, m0, seg, lane);
        NBAR(1);

        if (rr_ > 0) spin_ge(emptyv + s, rr_);
        __threadfence_block();
        __half* QP = (__half*)(sm + (s ? OFF_QP1 : OFF_QP0));
        #pragma unroll
        for (int mi = 0; mi < 2; mi++) {
            const int mrow = m0 + mi * 16;
            const float Mlo = rmax4(RMAX, mrow + r);
            const float Mhi = rmax4(RMAX, mrow + 8 + r);
            #pragma unroll
            for (int t = 0; t < 8; t++) {
                const int f = fbase + t * 8 + q2;
                __half2 lo2 = __floats2half2_rn(__expf(pr[mi][t][0] - Mlo) * 0.0625f,
                                                __expf(pr[mi][t][1] - Mlo) * 0.0625f);
                __half2 hi2 = __floats2half2_rn(__expf(pr[mi][t][2] - Mhi) * 0.0625f,
                                                __expf(pr[mi][t][3] - Mhi) * 0.0625f);
                *(__half2*)(QP + (mrow + r) * QP_S + f)     = lo2;
                *(__half2*)(QP + (mrow + 8 + r) * QP_S + f) = hi2;
            }
        }
        NBAR(1);
        // denom: warp w owns rows [w*8, w*8+8)
        {
            float* DNIs = DNI + s * 64;
            #pragma unroll
            for (int rr2 = 0; rr2 < 8; rr2++) {
                const int row = w * 8 + rr2;
                float sum = 0.f;
                #pragma unroll
                for (int j = 0; j < 8; j++) {
                    const int f = lane + 32 * j;
                    sum = fmaf(__half2float(QP[row * QP_S + f]), KSS[f], sum);
                }
                #pragma unroll
                for (int off = 16; off > 0; off >>= 1)
                    sum += __shfl_xor_sync(0xffffffffu, sum, off);
                if (lane == 0) DNIs[row] = 1.0f / sum;
            }
        }
        NBAR(1);
        __threadfence_block();
        if (tid == 0) fullv[s] = rr_ + 1;
    }
}

// ===========================================================================
// qside consumer (warps 8-15): out = (q' kv) * DNI, store
// ===========================================================================
__device__ void qside_B(float* __restrict__ out, int pair, int grp,
                        char* sm, uint32_t smu, int tid, int w, int lane,
                        volatile int* fullv, volatile int* emptyv) {
    const int wB = w - 8;
    const int r  = lane >> 2;
    const int q2 = (lane & 3) * 2;
    const int a4c264 = a4_const(lane, 264);
    const int b2c264 = b2_const(lane, 264);
    const uint32_t kvt_u = smu + OFF_KVT;
    float* DNI = (float*)(sm + OFF_DNI);

    for (int c = 0; c < CHUNKS_PER_GROUP; c++) {
        const int s = c & 1, rr_ = c >> 1;
        spin_ge(fullv + s, rr_ + 1);
        __threadfence_block();

        const uint32_t qp_u = smu + (s ? OFF_QP1 : OFF_QP0);
        const int om0 = (wB >> 1) * 16;
        const int nb  = (wB & 1) * 32;
        float oc[4][4];
        #pragma unroll
        for (int t = 0; t < 4; t++)
            #pragma unroll
            for (int u = 0; u < 4; u++) oc[t][u] = 0.f;

        #pragma unroll
        for (int k0 = 0; k0 < 256; k0 += 16) {
            unsigned a[4];
            ldsm4(a, qp_u + 2u * (om0 * QP_S + k0) + a4c264);
            #pragma unroll
            for (int t = 0; t < 4; t++) {
                unsigned b[2];
                ldsm2(b, kvt_u + 2u * ((nb + t * 8) * KVT_S + k0) + b2c264);
                mma16816(oc[t], a[0], a[1], a[2], a[3], b[0], b[1]);
            }
        }
        const float* DNIs = DNI + s * 64;
        const float ilo = DNIs[om0 + r];
        const float ihi = DNIs[om0 + 8 + r];
        float* od = out + ((size_t)pair * Np + grp * ROWS_PER_GROUP + c * CHUNK) * Dp;
        #pragma unroll
        for (int t = 0; t < 4; t++) {
            const int e = nb + t * 8 + q2;
            float2 v0 = make_float2(oc[t][0] * ilo, oc[t][1] * ilo);
            float2 v1 = make_float2(oc[t][2] * ihi, oc[t][3] * ihi);
            *(float2*)&od[(om0 + r) * Dp + e]     = v0;
            *(float2*)&od[(om0 + 8 + r) * Dp + e] = v1;
        }
        NBAR(2);
        __threadfence_block();
        if (tid == 256) emptyv[s] = rr_ + 1;
    }
}

// ===========================================================================
__global__ __launch_bounds__(NT, 1)
void fused_kernel(const float* __restrict__ Q, const float* __restrict__ K,
                  const float* __restrict__ V, const float* __restrict__ P,
                  float* __restrict__ out) {
    extern __shared__ char sm[];
    __shared__ int jobS;

    const int tid  = threadIdx.x;
    const int w    = tid >> 5;
    const int lane = tid & 31;
    const uint32_t smu = (uint32_t)__cvta_generic_to_shared(sm);
    volatile int* fullv  = (volatile int*)(sm + OFF_FLG);
    volatile int* emptyv = fullv + 2;

    load_PT(P, (__half*)(sm + OFF_PTH), (__half*)(sm + OFF_PTL), tid);
    // ones columns (e=64..71) of both V stage buffers, written once
    if (tid < 128) {
        int b = tid >> 6, row = tid & 63;
        __half* Vs = (__half*)(sm + (b ? OFF_V1 : OFF_V0));
        uint4 z = make_uint4(pack2(__float2half_rn(1.0f), __float2half_rn(0.0f)),
                             pack2(__float2half_rn(0.0f), __float2half_rn(0.0f)),
                             pack2(__float2half_rn(0.0f), __float2half_rn(0.0f)),
                             pack2(__float2half_rn(0.0f), __float2half_rn(0.0f)));
        *(uint4*)(Vs + row * V_S + 64) = z;
    }
    __syncthreads();

    // ---- phase 1: kside ----
    for (;;) {
        if (tid == 0) {
            jobS = (int)atomicAdd(&g_jobk, 1u);
            fullv[0] = 0; fullv[1] = 0; emptyv[0] = 0; emptyv[1] = 0;
        }
        __syncthreads();
        const int j = jobS;
        if (j >= NJOBS) break;
        const int pair = j / GROUPS, grp = j % GROUPS;
        if (w < 8) kside_A(K, pair, grp, sm, smu, tid, w, lane, fullv, emptyv);
        else       kside_B(V, pair, grp, sm, smu, tid, w, lane, fullv, emptyv);
        __syncthreads();
    }

    // ---- phase 2: qside ----
    int prev_pair = -1;
    for (;;) {
        if (tid == 0) {
            jobS = (int)atomicAdd(&g_jobq, 1u);
            fullv[0] = 0; fullv[1] = 0; emptyv[0] = 0; emptyv[1] = 0;
        }
        __syncthreads();
        const int j = jobS;
        if (j >= NJOBS) break;
        const int pair = j / GROUPS, grp = j % GROUPS;
        if (pair != prev_pair) {
            if (tid == 0) {
                while (atomicAdd(&g_sync[pair], 0u) < (unsigned)GROUPS) __nanosleep(100);
            }
            __syncthreads();
            __threadfence();
            // load kv -> KVT [e][f] f16, ksum -> KSS
            __half* KVTh = (__half*)(sm + OFF_KVT);
            const float4* kvg = (const float4*)(g_kv + (size_t)pair * Fp * Dp);
            for (int jj = tid; jj < Fp * Dp / 4; jj += NT) {
                float4 v = __ldcg(&kvg[jj]);
                int f = jj >> 4;
                int e0 = (jj & 15) * 4;
                #pragma unroll
                for (int u = 0; u < 4; u++)
                    KVTh[(e0 + u) * KVT_S + f] = __float2half_rn((&v.x)[u]);
            }
            if (tid < Fp) ((float*)(sm + OFF_KSS))[tid] = __ldcg(&g_ksum[(size_t)pair * Fp + tid]) + 1e-6f;
            __syncthreads();
            prev_pair = pair;
        }
        if (w < 8) qside_A(Q, pair, grp, sm, smu, tid, w, lane, fullv, emptyv);
        else       qside_B(out, pair, grp, sm, smu, tid, w, lane, fullv, emptyv);
        __syncthreads();
    }
}

// ---------------------------------------------------------------------------
extern "C" void kernel_launch(void* const* d_in, const int* in_sizes, int n_in,
                              void* d_out, int out_size) {
    const float* q = (const float*)d_in[0];
    const float* k = (const float*)d_in[1];
    const float* v = (const float*)d_in[2];
    const float* p = (const float*)d_in[3];
    float* out = (float*)d_out;

    cudaFuncSetAttribute(fused_kernel, cudaFuncAttributeMaxDynamicSharedMemorySize, (int)SMEM_TOTAL);

    {
        int total = BHp * Fp * Dp;
        zero_scratch<<<(total + 255) / 256, 256>>>();
    }
    fused_kernel<<<NCTA, NT, SMEM_TOTAL>>>(q, k, v, p, out);
}

// round 17
// speedup vs baseline: 1.5130x; 1.5130x over previous
#include <cuda_runtime.h>
#include <cuda_fp16.h>
#include <cstdint>

// Problem constants: B=2,H=16,N=4096,D=64,F=256
#define BHp   32
#define Np    4096
#define Dp    64
#define Fp    256
#define CHUNK 64
#define GROUPS 16
#define ROWS_PER_GROUP 256
#define CHUNKS_PER_GROUP 4
#define NJOBS (BHp * GROUPS)
#define NCTA  148
#define NT    512

// strides in halves
#define XS_S  72
#define PT_S  72
#define V_S   72
#define KP_S  264
#define QP_S  264
#define KVT_S 264

// smem byte offsets
#define OFF_PTH   0u
#define OFF_PTL   36864u
#define U0        73728u
#define OFF_SK    (U0)             // 16384
#define OFF_SV    (U0 + 16384u)
#define OFF_SQ    (U0)
#define OFF_XSH   (U0 + 32768u)    // 9216
#define OFF_XSL   (U0 + 41984u)    // 9216
#define OFF_V0    (U0 + 51200u)    // 9216
#define OFF_V1    (U0 + 60416u)    // 9216
#define OFF_KP    (U0 + 69632u)    // 33792
#define OFF_RMK   (U0 + 103424u)   // 1024
// qside aliases (V0 onward)
#define OFF_QP    (U0 + 51200u)    // 33792
#define OFF_KVT   (U0 + 84992u)    // 33792
#define OFF_KSS   (U0 + 118784u)   // 1024
#define OFF_RMQ   (U0 + 119808u)   // 1024
#define OFF_DNI   (U0 + 120832u)   // [2][64] f32 = 512
#define SMEM_TOTAL (U0 + 121344u)

__device__ float g_kv[BHp * Fp * Dp];
__device__ float g_ksum[BHp * Fp];
__device__ unsigned g_sync[BHp];
__device__ unsigned g_jobk;
__device__ unsigned g_jobq;

__global__ void zero_scratch() {
    int i = blockIdx.x * blockDim.x + threadIdx.x;
    if (i < BHp * Fp * Dp) g_kv[i] = 0.0f;
    if (i < BHp * Fp)      g_ksum[i] = 0.0f;
    if (i < BHp)           g_sync[i] = 0u;
    if (i == 0) { g_jobk = 0u; g_jobq = 0u; }
}

__device__ __forceinline__ void mma16816(float* c,
                                         unsigned a0, unsigned a1, unsigned a2, unsigned a3,
                                         unsigned b0, unsigned b1) {
    asm volatile(
        "mma.sync.aligned.m16n8k16.row.col.f32.f16.f16.f32 "
        "{%0,%1,%2,%3},{%4,%5,%6,%7},{%8,%9},{%0,%1,%2,%3};"
        : "+f"(c[0]), "+f"(c[1]), "+f"(c[2]), "+f"(c[3])
        : "r"(a0), "r"(a1), "r"(a2), "r"(a3), "r"(b0), "r"(b1));
}
__device__ __forceinline__ void ldsm4(unsigned* r, uint32_t a) {
    asm volatile("ldmatrix.sync.aligned.m8n8.x4.shared.b16 {%0,%1,%2,%3}, [%4];"
        : "=r"(r[0]), "=r"(r[1]), "=r"(r[2]), "=r"(r[3]) : "r"(a));
}
__device__ __forceinline__ void ldsm2(unsigned* r, uint32_t a) {
    asm volatile("ldmatrix.sync.aligned.m8n8.x2.shared.b16 {%0,%1}, [%2];"
        : "=r"(r[0]), "=r"(r[1]) : "r"(a));
}
__device__ __forceinline__ void ldsm4t(unsigned* r, uint32_t a) {
    asm volatile("ldmatrix.sync.aligned.m8n8.x4.trans.shared.b16 {%0,%1,%2,%3}, [%4];"
        : "=r"(r[0]), "=r"(r[1]), "=r"(r[2]), "=r"(r[3]) : "r"(a));
}
__device__ __forceinline__ void ldsm2t(unsigned* r, uint32_t a) {
    asm volatile("ldmatrix.sync.aligned.m8n8.x2.trans.shared.b16 {%0,%1}, [%2];"
        : "=r"(r[0]), "=r"(r[1]) : "r"(a));
}

__device__ __forceinline__ void cpasync16(void* dst_smem, const void* src) {
    uint32_t d = (uint32_t)__cvta_generic_to_shared(dst_smem);
    asm volatile("cp.async.cg.shared.global [%0], [%1], 16;" :: "r"(d), "l"(src));
}
#define CP_COMMIT() asm volatile("cp.async.commit_group;" ::: "memory")
#define CP_WAIT0()  asm volatile("cp.async.wait_group 0;" ::: "memory")

__device__ __forceinline__ void load_PT(const float* __restrict__ P,
                                        __half* PTh, __half* PTl, int tid) {
    for (int j = tid; j < Dp * Fp / 4; j += NT) {
        float4 v = ((const float4*)P)[j];
        int d = j >> 6;
        int f0 = (j & 63) * 4;
        #pragma unroll
        for (int u = 0; u < 4; u++) {
            float x = (&v.x)[u];
            __half hi = __float2half_rn(x);
            __half lo = __float2half_rn(x - __half2float(hi));
            PTh[(f0 + u) * PT_S + d] = hi;
            PTl[(f0 + u) * PT_S + d] = lo;
        }
    }
}

// ldmatrix lane-constant byte offsets
__device__ __forceinline__ int a4_const(int lane, int S) {
    return 2 * (((lane & 7) + ((lane >> 3) & 1) * 8) * S + (lane >> 4) * 8);
}
__device__ __forceinline__ int b2_const(int lane, int S) {
    return 2 * ((lane & 7) * S + ((lane >> 3) & 1) * 8);
}
__device__ __forceinline__ int a4t_const(int lane, int S) {
    return 2 * ((lane & 7) * S) + (((lane >> 3) & 1) * 16) + (((lane >> 4) & 1) * 2 * 8 * S);
}
__device__ __forceinline__ int b2t_const(int lane, int S) {
    int l = lane & 15;
    return 2 * ((l & 7) * S) + ((l >> 3) * 2 * 8 * S);
}

__device__ __forceinline__ void rowmax_store(float pr[8][4], float* RMAX,
                                             int m0, int seg, int lane) {
    const int r = lane >> 2;
    float mlo = -3.4e38f, mhi = -3.4e38f;
    #pragma unroll
    for (int t = 0; t < 8; t++) {
        mlo = fmaxf(mlo, fmaxf(pr[t][0], pr[t][1]));
        mhi = fmaxf(mhi, fmaxf(pr[t][2], pr[t][3]));
    }
    #pragma unroll
    for (int off = 1; off <= 2; off <<= 1) {
        mlo = fmaxf(mlo, __shfl_xor_sync(0xffffffffu, mlo, off));
        mhi = fmaxf(mhi, __shfl_xor_sync(0xffffffffu, mhi, off));
    }
    if ((lane & 3) == 0) {
        RMAX[seg * 64 + m0 + r]     = mlo;
        RMAX[seg * 64 + m0 + 8 + r] = mhi;
    }
}
__device__ __forceinline__ float rmax4(const float* RMAX, int row) {
    return fmaxf(fmaxf(RMAX[row], RMAX[64 + row]),
                 fmaxf(RMAX[128 + row], RMAX[192 + row]));
}
__device__ __forceinline__ unsigned pack2(__half a, __half b) {
    __half2 h = __halves2half2(a, b);
    return *(unsigned*)&h;
}

// ---------------------------------------------------------------------------
// kside: interleaves kv-mma(c-1) with proj-mma(c)
// ---------------------------------------------------------------------------
__device__ void kside_job(const float* __restrict__ K, const float* __restrict__ V,
                          int pair, int grp, char* sm, uint32_t smu,
                          int tid, int w, int lane) {
    __half* XSh = (__half*)(sm + OFF_XSH);
    __half* XSl = (__half*)(sm + OFF_XSL);
    __half* KP  = (__half*)(sm + OFF_KP);
    float*  RMAX = (float*)(sm + OFF_RMK);
    float4* SK = (float4*)(sm + OFF_SK);
    float4* SV = (float4*)(sm + OFF_SV);

    const uint32_t xsh_u = smu + OFF_XSH, xsl_u = smu + OFF_XSL;
    const uint32_t pth_u = smu + OFF_PTH, ptl_u = smu + OFF_PTL;
    const uint32_t kp_u  = smu + OFF_KP;

    const int r  = lane >> 2;
    const int q2 = (lane & 3) * 2;
    const int a4c72 = a4_const(lane, 72);
    const int b2c72 = b2_const(lane, 72);
    const int at4   = a4t_const(lane, KP_S);
    const int bt2   = b2t_const(lane, V_S);
    const int m0 = (w >> 2) * 16;
    const int seg = w & 3;
    const int fbase = seg * 64;
    const int fw = w * 16;

    {
        const float4* ksrc = (const float4*)(K + ((size_t)pair * Np + grp * ROWS_PER_GROUP) * Dp);
        const float4* vsrc = (const float4*)(V + ((size_t)pair * Np + grp * ROWS_PER_GROUP) * Dp);
        #pragma unroll
        for (int i = 0; i < 2; i++) {
            int j = tid + NT * i;
            cpasync16(&SK[j], &ksrc[j]);
            cpasync16(&SV[j], &vsrc[j]);
        }
        CP_COMMIT();
    }

    float accv[9][4];
    #pragma unroll
    for (int t = 0; t < 9; t++)
        #pragma unroll
        for (int u = 0; u < 4; u++) accv[t][u] = 0.f;

    for (int c = 0; c < CHUNKS_PER_GROUP; c++) {
        CP_WAIT0();
        __half* Vs = (__half*)(sm + ((c & 1) ? OFF_V1 : OFF_V0));
        #pragma unroll
        for (int i = 0; i < 2; i++) {
            int j = tid + NT * i;
            float4 xv = SK[j];
            float4 vv = SV[j];
            int rr = j >> 4, d0 = (j & 15) * 4;
            __half h[4], l[4], vh[4];
            #pragma unroll
            for (int u = 0; u < 4; u++) {
                float x = (&xv.x)[u];
                h[u] = __float2half_rn(x);
                l[u] = __float2half_rn(x - __half2float(h[u]));
                vh[u] = __float2half_rn((&vv.x)[u]);
            }
            *(uint2*)(XSh + rr * XS_S + d0) = make_uint2(pack2(h[0], h[1]), pack2(h[2], h[3]));
            *(uint2*)(XSl + rr * XS_S + d0) = make_uint2(pack2(l[0], l[1]), pack2(l[2], l[3]));
            *(uint2*)(Vs + rr * V_S + d0)   = make_uint2(pack2(vh[0], vh[1]), pack2(vh[2], vh[3]));
        }
        __syncthreads();

        if (c + 1 < CHUNKS_PER_GROUP) {
            const int row1 = grp * ROWS_PER_GROUP + (c + 1) * CHUNK;
            const float4* ksrc = (const float4*)(K + ((size_t)pair * Np + row1) * Dp);
            const float4* vsrc = (const float4*)(V + ((size_t)pair * Np + row1) * Dp);
            #pragma unroll
            for (int i = 0; i < 2; i++) {
                int j = tid + NT * i;
                cpasync16(&SK[j], &ksrc[j]);
                cpasync16(&SV[j], &vsrc[j]);
            }
            CP_COMMIT();
        }

        // phase II: proj(c) interleaved with kv(c-1)
        const uint32_t vprev_u = smu + ((c & 1) ? OFF_V0 : OFF_V1);  // V[(c-1)&1]
        float pr[8][4];
        #pragma unroll
        for (int t = 0; t < 8; t++) {
            pr[t][0] = 0.f; pr[t][1] = 0.f; pr[t][2] = 0.f; pr[t][3] = 0.f;
        }
        #pragma unroll
        for (int k0 = 0; k0 < 64; k0 += 16) {
            unsigned ah[4], al[4];
            uint32_t ab = 2u * (m0 * XS_S + k0) + a4c72;
            ldsm4(ah, xsh_u + ab);
            ldsm4(al, xsl_u + ab);
            if (c > 0) {
                unsigned a[4];
                ldsm4t(a, kp_u + 2u * (k0 * KP_S + fw) + at4);
                #pragma unroll
                for (int t = 0; t < 9; t++) {
                    unsigned b[2];
                    ldsm2t(b, vprev_u + 2u * (k0 * V_S + t * 8) + bt2);
                    mma16816(accv[t], a[0], a[1], a[2], a[3], b[0], b[1]);
                }
            }
            #pragma unroll
            for (int t = 0; t < 8; t++) {
                uint32_t bb = 2u * ((fbase + t * 8) * PT_S + k0) + b2c72;
                unsigned bh[2], bl[2];
                ldsm2(bh, pth_u + bb);
                ldsm2(bl, ptl_u + bb);
                mma16816(pr[t], ah[0], ah[1], ah[2], ah[3], bh[0], bh[1]);
                mma16816(pr[t], ah[0], ah[1], ah[2], ah[3], bl[0], bl[1]);
                mma16816(pr[t], al[0], al[1], al[2], al[3], bh[0], bh[1]);
            }
        }
        rowmax_store(pr, RMAX, m0, seg, lane);
        __syncthreads();

        // phase III: exp -> KP row-major
        {
            const float Mlo = rmax4(RMAX, m0 + r);
            const float Mhi = rmax4(RMAX, m0 + 8 + r);
            #pragma unroll
            for (int t = 0; t < 8; t++) {
                const int f = fbase + t * 8 + q2;
                __half2 lo2 = __floats2half2_rn(__expf(pr[t][0] - Mlo) * 0.0625f,
                                                __expf(pr[t][1] - Mlo) * 0.0625f);
                __half2 hi2 = __floats2half2_rn(__expf(pr[t][2] - Mhi) * 0.0625f,
                                                __expf(pr[t][3] - Mhi) * 0.0625f);
                *(__half2*)(KP + (m0 + r) * KP_S + f)     = lo2;
                *(__half2*)(KP + (m0 + 8 + r) * KP_S + f) = hi2;
            }
        }
        __syncthreads();
    }

    // epilogue: kv for last chunk (c=3, V buffer parity 1)
    {
        const uint32_t vlast_u = smu + OFF_V1;
        #pragma unroll
        for (int k0 = 0; k0 < 64; k0 += 16) {
            unsigned a[4];
            ldsm4t(a, kp_u + 2u * (k0 * KP_S + fw) + at4);
            #pragma unroll
            for (int t = 0; t < 9; t++) {
                unsigned b[2];
                ldsm2t(b, vlast_u + 2u * (k0 * V_S + t * 8) + bt2);
                mma16816(accv[t], a[0], a[1], a[2], a[3], b[0], b[1]);
            }
        }
    }

    float* kvg = g_kv + (size_t)pair * Fp * Dp;
    {
        const int f0 = fw + r;
        #pragma unroll
        for (int t = 0; t < 8; t++) {
            const int e = t * 8 + q2;
            atomicAdd(&kvg[f0 * Dp + e],           accv[t][0]);
            atomicAdd(&kvg[f0 * Dp + e + 1],       accv[t][1]);
            atomicAdd(&kvg[(f0 + 8) * Dp + e],     accv[t][2]);
            atomicAdd(&kvg[(f0 + 8) * Dp + e + 1], accv[t][3]);
        }
        if ((lane & 3) == 0) {
            atomicAdd(&g_ksum[(size_t)pair * Fp + f0],     accv[8][0]);
            atomicAdd(&g_ksum[(size_t)pair * Fp + f0 + 8], accv[8][2]);
        }
    }
    __syncthreads();
    __threadfence();
    if (tid == 0) atomicAdd(&g_sync[pair], 1u);
}

// ---------------------------------------------------------------------------
// qside: interleaves out-mma(c-1) with proj-mma(c)
// ---------------------------------------------------------------------------
__device__ void qside_job(const float* __restrict__ Q, float* __restrict__ out,
                          int pair, int grp, bool reload_kv, char* sm, uint32_t smu,
                          int tid, int w, int lane) {
    __half* XSh = (__half*)(sm + OFF_XSH);
    __half* XSl = (__half*)(sm + OFF_XSL);
    __half* QP  = (__half*)(sm + OFF_QP);
    __half* KVTh = (__half*)(sm + OFF_KVT);
    float*  KSS  = (float*)(sm + OFF_KSS);
    float*  RMAX = (float*)(sm + OFF_RMQ);
    float*  DNI  = (float*)(sm + OFF_DNI);
    float4* SQ   = (float4*)(sm + OFF_SQ);

    const uint32_t xsh_u = smu + OFF_XSH, xsl_u = smu + OFF_XSL;
    const uint32_t pth_u = smu + OFF_PTH, ptl_u = smu + OFF_PTL;
    const uint32_t qp_u  = smu + OFF_QP,  kvt_u = smu + OFF_KVT;

    const int r  = lane >> 2;
    const int q2 = (lane & 3) * 2;
    const int a4c72  = a4_const(lane, 72);
    const int b2c72  = b2_const(lane, 72);
    const int a4c264 = a4_const(lane, 264);
    const int b2c264 = b2_const(lane, 264);
    const int m0 = (w >> 2) * 16;
    const int seg = w & 3;
    const int fbase = seg * 64;
    const int om0 = (w >> 2) * 16;
    const int nb  = (w & 3) * 16;

    {
        const float4* qsrc = (const float4*)(Q + ((size_t)pair * Np + grp * ROWS_PER_GROUP) * Dp);
        #pragma unroll
        for (int i = 0; i < 2; i++) {
            int j = tid + NT * i;
            cpasync16(&SQ[j], &qsrc[j]);
        }
        CP_COMMIT();
    }

    if (reload_kv) {
        const float4* kvg = (const float4*)(g_kv + (size_t)pair * Fp * Dp);
        for (int j = tid; j < Fp * Dp / 4; j += NT) {
            float4 v = __ldcg(&kvg[j]);
            int f = j >> 4;
            int e0 = (j & 15) * 4;
            #pragma unroll
            for (int u = 0; u < 4; u++)
                KVTh[(e0 + u) * KVT_S + f] = __float2half_rn((&v.x)[u]);
        }
        if (tid < Fp) KSS[tid] = __ldcg(&g_ksum[(size_t)pair * Fp + tid]) + 1e-6f;
    }

    for (int c = 0; c < CHUNKS_PER_GROUP; c++) {
        CP_WAIT0();
        #pragma unroll
        for (int i = 0; i < 2; i++) {
            int j = tid + NT * i;
            float4 xv = SQ[j];
            int rr = j >> 4, d0 = (j & 15) * 4;
            __half h[4], l[4];
            #pragma unroll
            for (int u = 0; u < 4; u++) {
                float x = (&xv.x)[u];
                h[u] = __float2half_rn(x);
                l[u] = __float2half_rn(x - __half2float(h[u]));
            }
            *(uint2*)(XSh + rr * XS_S + d0) = make_uint2(pack2(h[0], h[1]), pack2(h[2], h[3]));
            *(uint2*)(XSl + rr * XS_S + d0) = make_uint2(pack2(l[0], l[1]), pack2(l[2], l[3]));
        }
        __syncthreads();

        if (c + 1 < CHUNKS_PER_GROUP) {
            const int row1 = grp * ROWS_PER_GROUP + (c + 1) * CHUNK;
            const float4* qsrc = (const float4*)(Q + ((size_t)pair * Np + row1) * Dp);
            #pragma unroll
            for (int i = 0; i < 2; i++) {
                int j = tid + NT * i;
                cpasync16(&SQ[j], &qsrc[j]);
            }
            CP_COMMIT();
        }

        // phase II: proj(c) interleaved with out(c-1)
        float pr[8][4];
        #pragma unroll
        for (int t = 0; t < 8; t++) {
            pr[t][0] = 0.f; pr[t][1] = 0.f; pr[t][2] = 0.f; pr[t][3] = 0.f;
        }
        float oc[2][4];
        #pragma unroll
        for (int t = 0; t < 2; t++)
            #pragma unroll
            for (int u = 0; u < 4; u++) oc[t][u] = 0.f;

        #pragma unroll
        for (int k0 = 0; k0 < 64; k0 += 16) {
            unsigned ah[4], al[4];
            uint32_t ab = 2u * (m0 * XS_S + k0) + a4c72;
            ldsm4(ah, xsh_u + ab);
            ldsm4(al, xsl_u + ab);
            if (c > 0) {
                // out(c-1): 4 of 16 k-steps per proj k0 (256 total / 4)
                #pragma unroll
                for (int kk = 0; kk < 4; kk++) {
                    const int ko = k0 * 4 + kk * 16;
                    unsigned a[4];
                    ldsm4(a, qp_u + 2u * (om0 * QP_S + ko) + a4c264);
                    #pragma unroll
                    for (int t = 0; t < 2; t++) {
                        unsigned b[2];
                        ldsm2(b, kvt_u + 2u * ((nb + t * 8) * KVT_S + ko) + b2c264);
                        mma16816(oc[t], a[0], a[1], a[2], a[3], b[0], b[1]);
                    }
                }
            }
            #pragma unroll
            for (int t = 0; t < 8; t++) {
                uint32_t bb = 2u * ((fbase + t * 8) * PT_S + k0) + b2c72;
                unsigned bh[2], bl[2];
                ldsm2(bh, pth_u + bb);
                ldsm2(bl, ptl_u + bb);
                mma16816(pr[t], ah[0], ah[1], ah[2], ah[3], bh[0], bh[1]);
                mma16816(pr[t], ah[0], ah[1], ah[2], ah[3], bl[0], bl[1]);
                mma16816(pr[t], al[0], al[1], al[2], al[3], bh[0], bh[1]);
            }
        }
        if (c > 0) {
            const float* DNIs = DNI + ((c - 1) & 1) * 64;
            const float ilo = DNIs[om0 + r];
            const float ihi = DNIs[om0 + 8 + r];
            float* od = out + ((size_t)pair * Np + grp * ROWS_PER_GROUP + (c - 1) * CHUNK) * Dp;
            #pragma unroll
            for (int t = 0; t < 2; t++) {
                const int e = nb + t * 8 + q2;
                float2 v0 = make_float2(oc[t][0] * ilo, oc[t][1] * ilo);
                float2 v1 = make_float2(oc[t][2] * ihi, oc[t][3] * ihi);
                *(float2*)&od[(om0 + r) * Dp + e]     = v0;
                *(float2*)&od[(om0 + 8 + r) * Dp + e] = v1;
            }
        }
        rowmax_store(pr, RMAX, m0, seg, lane);
        __syncthreads();

        // phase III: exp -> QP, then denom -> DNI[c&1]
        {
            const float Mlo = rmax4(RMAX, m0 + r);
            const float Mhi = rmax4(RMAX, m0 + 8 + r);
            #pragma unroll
            for (int t = 0; t < 8; t++) {
                const int f = fbase + t * 8 + q2;
                __half2 lo2 = __floats2half2_rn(__expf(pr[t][0] - Mlo) * 0.0625f,
                                                __expf(pr[t][1] - Mlo) * 0.0625f);
                __half2 hi2 = __floats2half2_rn(__expf(pr[t][2] - Mhi) * 0.0625f,
                                                __expf(pr[t][3] - Mhi) * 0.0625f);
                *(__half2*)(QP + (m0 + r) * QP_S + f)     = lo2;
                *(__half2*)(QP + (m0 + 8 + r) * QP_S + f) = hi2;
            }
        }
        __syncthreads();
        {
            float* DNIs = DNI + (c & 1) * 64;
            #pragma unroll
            for (int rr2 = 0; rr2 < 4; rr2++) {
                const int row = w * 4 + rr2;
                float s = 0.f;
                #pragma unroll
                for (int j = 0; j < 8; j++) {
                    const int f = lane + 32 * j;
                    s = fmaf(__half2float(QP[row * QP_S + f]), KSS[f], s);
                }
                #pragma unroll
                for (int off = 16; off > 0; off >>= 1)
                    s += __shfl_xor_sync(0xffffffffu, s, off);
                if (lane == 0) DNIs[row] = 1.0f / s;
            }
        }
        __syncthreads();
    }

    // epilogue: out for last chunk (c=3, DNI parity 1)
    {
        float oc[2][4];
        #pragma unroll
        for (int t = 0; t < 2; t++)
            #pragma unroll
            for (int u = 0; u < 4; u++) oc[t][u] = 0.f;
        #pragma unroll
        for (int ko = 0; ko < 256; ko += 16) {
            unsigned a[4];
            ldsm4(a, qp_u + 2u * (om0 * QP_S + ko) + a4c264);
            #pragma unroll
            for (int t = 0; t < 2; t++) {
                unsigned b[2];
                ldsm2(b, kvt_u + 2u * ((nb + t * 8) * KVT_S + ko) + b2c264);
                mma16816(oc[t], a[0], a[1], a[2], a[3], b[0], b[1]);
            }
        }
        const float* DNIs = DNI + 64;
        const float ilo = DNIs[om0 + r];
        const float ihi = DNIs[om0 + 8 + r];
        float* od = out + ((size_t)pair * Np + grp * ROWS_PER_GROUP + 3 * CHUNK) * Dp;
        #pragma unroll
        for (int t = 0; t < 2; t++) {
            const int e = nb + t * 8 + q2;
            float2 v0 = make_float2(oc[t][0] * ilo, oc[t][1] * ilo);
            float2 v1 = make_float2(oc[t][2] * ihi, oc[t][3] * ihi);
            *(float2*)&od[(om0 + r) * Dp + e]     = v0;
            *(float2*)&od[(om0 + 8 + r) * Dp + e] = v1;
        }
    }
}

// ---------------------------------------------------------------------------
__global__ __launch_bounds__(NT, 1)
void fused_kernel(const float* __restrict__ Q, const float* __restrict__ K,
                  const float* __restrict__ V, const float* __restrict__ P,
                  float* __restrict__ out) {
    extern __shared__ char sm[];
    __shared__ int jobS;

    const int tid  = threadIdx.x;
    const int w    = tid >> 5;
    const int lane = tid & 31;
    const uint32_t smu = (uint32_t)__cvta_generic_to_shared(sm);

    load_PT(P, (__half*)(sm + OFF_PTH), (__half*)(sm + OFF_PTL), tid);
    // ones columns e=64..71 of both V buffers (persist through phase 1)
    if (tid < 128) {
        int b = tid >> 6, row = tid & 63;
        __half* Vs = (__half*)(sm + (b ? OFF_V1 : OFF_V0));
        uint4 z = make_uint4(pack2(__float2half_rn(1.0f), __float2half_rn(0.0f)),
                             pack2(__float2half_rn(0.0f), __float2half_rn(0.0f)),
                             pack2(__float2half_rn(0.0f), __float2half_rn(0.0f)),
                             pack2(__float2half_rn(0.0f), __float2half_rn(0.0f)));
        *(uint4*)(Vs + row * V_S + 64) = z;
    }
    __syncthreads();

    for (;;) {
        if (tid == 0) jobS = (int)atomicAdd(&g_jobk, 1u);
        __syncthreads();
        const int j = jobS;
        if (j >= NJOBS) break;
        kside_job(K, V, j / GROUPS, j % GROUPS, sm, smu, tid, w, lane);
        __syncthreads();
    }

    int prev_pair = -1;
    for (;;) {
        if (tid == 0) jobS = (int)atomicAdd(&g_jobq, 1u);
        __syncthreads();
        const int j = jobS;
        if (j >= NJOBS) break;
        const int pair = j / GROUPS;
        const int grp  = j % GROUPS;
        const bool reload = (pair != prev_pair);
        if (reload) {
            if (tid == 0) {
                while (atomicAdd(&g_sync[pair], 0u) < (unsigned)GROUPS) __nanosleep(100);
            }
            __syncthreads();
            __threadfence();
            prev_pair = pair;
        }
        qside_job(Q, out, pair, grp, reload, sm, smu, tid, w, lane);
        __syncthreads();
    }
}

// ---------------------------------------------------------------------------
extern "C" void kernel_launch(void* const* d_in, const int* in_sizes, int n_in,
                              void* d_out, int out_size) {
    const float* q = (const float*)d_in[0];
    const float* k = (const float*)d_in[1];
    const float* v = (const float*)d_in[2];
    const float* p = (const float*)d_in[3];
    float* out = (float*)d_out;

    cudaFuncSetAttribute(fused_kernel, cudaFuncAttributeMaxDynamicSharedMemorySize, (int)SMEM_TOTAL);

    {
        int total = BHp * Fp * Dp;
        zero_scratch<<<(total + 255) / 256, 256>>>();
    }
    fused_kernel<<<NCTA, NT, SMEM_TOTAL>>>(q, k, v, p, out);
}